// round 13
// baseline (speedup 1.0000x reference)
#include <cuda_runtime.h>
#include <cstdint>

// input f32 [4,64,512,512], gathered f32 [2048,64,16,16], indices (b,hb,wb)
// int32 or int64 (detected on device, cheaply). stride==kernel==16 -> 4096
// disjoint 16x16 slots; duplicates via per-slot linked lists. Main pass:
// out = in + sum(patches in slot), 640MB traffic, 256-bit streaming accesses
// (read streams via non-coherent path), one-shot 32768x256 grid.
//
// Locked-in findings: persistent+prefetch loses 25us (occupancy/serialization);
// PDL is neutral-to-negative (main CTAs ramp early, absorb build tail);
// epoch-heads remove the init kernel; joint layout analysis: in/out 1KB/warp
// contiguous forces gathered to 64B/patch-row segments -- already achieved,
// no remap can beat it. Heads are u64 (epoch<<32|patch); g_ctr bumps once per
// build block (8/launch) so all blocks of one launch share epoch=(ctr>>3)+1
// (launches stream-serialized); stale heads fail the epoch compare.

#define BB 4
#define CC 64
#define HH 512
#define WW 512
#define NN 2048
#define NSLOTS 4096   // BB * 32 * 32

__device__ unsigned long long g_slot[NSLOTS];  // (epoch<<32) | patch_id
__device__ int g_next[NN];
__device__ unsigned g_ctr;                     // monotonic, +8 per launch

// 8 blocks x 256 threads = exactly NN.
// Cheap dtype detect per block: each thread checks ONE u64 of the first
// 256 words (2048B, always in-bounds: int32 buffer = 24576B). Genuine int64
// index values are < 512 -> high words all zero; int32 data read as u64
// carries a neighboring field in the high word (all-256-zero probability ~0).
__global__ void __launch_bounds__(256) build_lists_kernel(const void* __restrict__ idx_raw) {
    __shared__ unsigned s_epoch;
    __shared__ int s_is64;
    int t = threadIdx.x;
    if (t == 0) {
        s_epoch = (atomicAdd(&g_ctr, 1u) >> 3) + 1u;
        s_is64 = 1;
    }
    __syncthreads();

    const unsigned long long* w = (const unsigned long long*)idx_raw;
    if ((w[t] >> 32) != 0ull) s_is64 = 0;       // benign race
    __syncthreads();

    int n = blockIdx.x * 256 + t;               // < NN
    int b, hb, wb;
    if (s_is64) {
        const long long* idx = (const long long*)idx_raw;
        b  = (int)idx[3 * n + 0];
        hb = (int)idx[3 * n + 1];
        wb = (int)idx[3 * n + 2];
    } else {
        const int* idx = (const int*)idx_raw;
        b  = idx[3 * n + 0];
        hb = idx[3 * n + 1];
        wb = idx[3 * n + 2];
    }
    int slot = (b << 10) | (hb << 5) | wb;
    unsigned long long packed = ((unsigned long long)s_epoch << 32) | (unsigned)n;
    unsigned long long old = atomicExch(&g_slot[slot & (NSLOTS - 1)], packed);
    g_next[n] = ((unsigned)(old >> 32) == s_epoch) ? (int)(old & 0xffffffffu) : -1;
}

// read-only streams -> non-coherent path, evict-first
__device__ __forceinline__ void ldg256nc(const float* p, float* v) {
    asm volatile("ld.global.nc.cs.v8.f32 {%0,%1,%2,%3,%4,%5,%6,%7}, [%8];"
                 : "=f"(v[0]), "=f"(v[1]), "=f"(v[2]), "=f"(v[3]),
                   "=f"(v[4]), "=f"(v[5]), "=f"(v[6]), "=f"(v[7])
                 : "l"(p));
}

__device__ __forceinline__ void stg256cs(float* p, const float* v) {
    asm volatile("st.global.cs.v8.f32 [%0], {%1,%2,%3,%4,%5,%6,%7,%8};"
                 :: "l"(p),
                    "f"(v[0]), "f"(v[1]), "f"(v[2]), "f"(v[3]),
                    "f"(v[4]), "f"(v[5]), "f"(v[6]), "f"(v[7])
                 : "memory");
}

// One float8 (32B) per thread. 8,388,608 float8 -> 32768 blocks of 256.
__global__ void __launch_bounds__(256) scatter_main_kernel(
    const float* __restrict__ in,
    const float* __restrict__ g,
    float* __restrict__ out)
{
    unsigned i8 = blockIdx.x * 256u + threadIdx.x;   // < 2^23

    unsigned w8 = i8 & 63u;           // float8 column: w = w8*8
    unsigned h  = (i8 >> 6) & 511u;
    unsigned c  = (i8 >> 15) & 63u;
    unsigned b  = i8 >> 21;

    unsigned slot = (b << 10) | ((h >> 4) << 5) | (w8 >> 1);

    unsigned epoch = ((g_ctr - 1u) >> 3) + 1u;       // issue early: overlaps

    float v[8];
    ldg256nc(in + ((size_t)i8 << 3), v);

    unsigned long long hv = g_slot[slot];
    int p = ((unsigned)(hv >> 32) == epoch) ? (int)(hv & 0xffffffffu) : -1;

    if (p >= 0) {
        // patch offset in float8 units: p*2048 + c*32 + (h&15)*2 + (w8&1)
        unsigned local8 = (c << 5) | ((h & 15u) << 1) | (w8 & 1u);
        do {
            float gv[8];
            ldg256nc(g + (((size_t)((unsigned)p << 11) + local8) << 3), gv);
            #pragma unroll
            for (int j = 0; j < 8; j++) v[j] += gv[j];
            p = g_next[p];
        } while (p >= 0);
    }

    stg256cs(out + ((size_t)i8 << 3), v);
}

extern "C" void kernel_launch(void* const* d_in, const int* in_sizes, int n_in,
                              void* d_out, int out_size) {
    const float* input    = (const float*)d_in[0];
    const float* gathered = (const float*)d_in[1];
    const void*  indices  = d_in[2];
    float* out = (float*)d_out;

    build_lists_kernel<<<NN / 256, 256>>>(indices);

    const unsigned total8 = (unsigned)(BB * CC * HH * WW) / 8u;  // 8,388,608
    scatter_main_kernel<<<total8 / 256, 256>>>(input, gathered, out);
}